// round 1
// baseline (speedup 1.0000x reference)
#include <cuda_runtime.h>
#include <cstdint>

// Problem constants (fixed shapes for this problem)
#define CDIM   2048      // feature dim
#define EDIM   64        // experts
#define NTOT   128       // 64 route + 64 noise outputs
#define TOPK   8
#define M_TILE 64        // tokens per CTA
#define KB     32        // K chunk
#define XS_STRIDE 66     // 64 tokens + 2 pad (even -> lds.64 aligned)
#define WS_STRIDE 132    // 128 outputs + 4 pad (mult of 4 -> lds.128 aligned)

// ---- packed f32x2 helpers (sm_103a FFMA2 path) ----
__device__ __forceinline__ void fma2(unsigned long long &d, unsigned long long a,
                                     unsigned long long b) {
    asm("fma.rn.f32x2 %0, %1, %2, %0;" : "+l"(d) : "l"(a), "l"(b));
}
__device__ __forceinline__ unsigned long long pack2(float lo, float hi) {
    unsigned long long r;
    asm("mov.b64 %0, {%1, %2};" : "=l"(r) : "f"(lo), "f"(hi));
    return r;
}
__device__ __forceinline__ void unpack2(unsigned long long v, float &lo, float &hi) {
    asm("mov.b64 {%0, %1}, %2;" : "=f"(lo), "=f"(hi) : "l"(v));
}

__global__ __launch_bounds__(256, 2)
void noisy_topk_router_kernel(
    const float* __restrict__ x,        // [M, C]
    const float* __restrict__ w_route,  // [E, C]
    const float* __restrict__ w_noise,  // [E, C]
    const float* __restrict__ noise,    // [M, E]
    float* __restrict__ out_router,     // [M, E]
    float* __restrict__ out_indices,    // [M, K] (as float)
    int write_indices)
{
    // Shared: GEMM tiles union'd with the logits buffer (reused after mainloop).
    __shared__ __align__(16) float smem[M_TILE * NTOT];   // 32 KB
    __shared__ float s_max[M_TILE];
    __shared__ float s_inv[M_TILE];
    __shared__ unsigned long long s_mask[M_TILE];

    float* Xs = smem;                       // [KB][XS_STRIDE]   (2112 floats)
    float* Ws = smem + KB * XS_STRIDE;      // [KB][WS_STRIDE]   (4224 floats)
    float* Ls = smem;                       // [M_TILE][NTOT]    (epilogue reuse)

    const int tid = threadIdx.x;
    const int tx  = tid & 31;   // output group: columns tx*4 .. tx*4+3
    const int ty  = tid >> 5;   // token group:  rows ty*8 .. ty*8+7
    const int tokBase = blockIdx.x * M_TILE;

    // 16 packed accumulators: acc[p][j] = (token 2p, token 2p+1) for output j
    unsigned long long acc[4][4];
#pragma unroll
    for (int p = 0; p < 4; ++p)
#pragma unroll
        for (int j = 0; j < 4; ++j) acc[p][j] = 0ULL;

    // fill mappings
    const int xf_t = tid >> 2;                 // 0..63 token row
    const int xf_c = tid & 3;                  // 0..3
    const int wf_o = tid >> 1;                 // 0..127 output row
    const int wf_c = tid & 1;                  // 0..1
    const float* xsrc = x + (size_t)(tokBase + xf_t) * CDIM;
    const float* wsrc = (wf_o < EDIM) ? (w_route + (size_t)wf_o * CDIM)
                                      : (w_noise + (size_t)(wf_o - EDIM) * CDIM);

    for (int k0 = 0; k0 < CDIM; k0 += KB) {
        __syncthreads();
        // --- X chunk: Xs[kk][t] = x[tokBase+t][k0+kk] ---
#pragma unroll
        for (int h = 0; h < 2; ++h) {
            const int kk = xf_c * 8 + h * 4;
            float4 v = *(const float4*)(xsrc + k0 + kk);
            Xs[(kk + 0) * XS_STRIDE + xf_t] = v.x;
            Xs[(kk + 1) * XS_STRIDE + xf_t] = v.y;
            Xs[(kk + 2) * XS_STRIDE + xf_t] = v.z;
            Xs[(kk + 3) * XS_STRIDE + xf_t] = v.w;
        }
        // --- W chunk: Ws[kk][o] = W[o][k0+kk]  (W = [route; noise]) ---
#pragma unroll
        for (int h = 0; h < 4; ++h) {
            const int kk = wf_c * 16 + h * 4;
            float4 v = *(const float4*)(wsrc + k0 + kk);
            Ws[(kk + 0) * WS_STRIDE + wf_o] = v.x;
            Ws[(kk + 1) * WS_STRIDE + wf_o] = v.y;
            Ws[(kk + 2) * WS_STRIDE + wf_o] = v.z;
            Ws[(kk + 3) * WS_STRIDE + wf_o] = v.w;
        }
        __syncthreads();

        // --- main FMA2 loop ---
#pragma unroll
        for (int kk = 0; kk < KB; ++kk) {
            const float* xrow = Xs + kk * XS_STRIDE + ty * 8;
            unsigned long long xp0 = *(const unsigned long long*)(xrow + 0);
            unsigned long long xp1 = *(const unsigned long long*)(xrow + 2);
            unsigned long long xp2 = *(const unsigned long long*)(xrow + 4);
            unsigned long long xp3 = *(const unsigned long long*)(xrow + 6);
            float4 w4 = *(const float4*)(Ws + kk * WS_STRIDE + tx * 4);
            unsigned long long wp0 = pack2(w4.x, w4.x);
            unsigned long long wp1 = pack2(w4.y, w4.y);
            unsigned long long wp2 = pack2(w4.z, w4.z);
            unsigned long long wp3 = pack2(w4.w, w4.w);
            fma2(acc[0][0], xp0, wp0); fma2(acc[0][1], xp0, wp1);
            fma2(acc[0][2], xp0, wp2); fma2(acc[0][3], xp0, wp3);
            fma2(acc[1][0], xp1, wp0); fma2(acc[1][1], xp1, wp1);
            fma2(acc[1][2], xp1, wp2); fma2(acc[1][3], xp1, wp3);
            fma2(acc[2][0], xp2, wp0); fma2(acc[2][1], xp2, wp1);
            fma2(acc[2][2], xp2, wp2); fma2(acc[2][3], xp2, wp3);
            fma2(acc[3][0], xp3, wp0); fma2(acc[3][1], xp3, wp1);
            fma2(acc[3][2], xp3, wp2); fma2(acc[3][3], xp3, wp3);
        }
    }

    // --- dump accumulators into Ls[token][output] ---
    __syncthreads();
#pragma unroll
    for (int p = 0; p < 4; ++p) {
        const int t0 = ty * 8 + 2 * p;
#pragma unroll
        for (int j = 0; j < 4; ++j) {
            float lo, hi;
            unpack2(acc[p][j], lo, hi);
            Ls[t0 * NTOT + tx * 4 + j]       = lo;
            Ls[(t0 + 1) * NTOT + tx * 4 + j] = hi;
        }
    }
    __syncthreads();

    // --- noisy logits: noisy = logit + noise * softplus(noise_logit) ---
    // writes [0,64), reads [64,128) -> no cross-thread hazard
    for (int i = tid; i < M_TILE * EDIM; i += 256) {
        const int t = i >> 6, e = i & 63;
        float l  = Ls[t * NTOT + e];
        float nl = Ls[t * NTOT + EDIM + e];
        float nz = noise[(size_t)(tokBase + t) * EDIM + e];
        // stable softplus = max(x,0) + log1p(exp(-|x|))  (matches jax.nn.softplus)
        float sp = fmaxf(nl, 0.0f) + log1pf(expf(-fabsf(nl)));
        Ls[t * NTOT + e] = fmaf(nz, sp, l);
    }
    __syncthreads();

    // --- per-token top-8 (stable: ties keep lower index, matches lax.top_k) ---
    if (tid < M_TILE) {
        const float* row = Ls + tid * NTOT;
        const float NEG_INF = __int_as_float(0xff800000);
        float best[TOPK];
        int   bidx[TOPK];
#pragma unroll
        for (int i = 0; i < TOPK; ++i) { best[i] = NEG_INF; bidx[i] = -1; }
        for (int e = 0; e < EDIM; ++e) {
            float v = row[e];
            if (v > best[TOPK - 1]) {
                best[TOPK - 1] = v; bidx[TOPK - 1] = e;
#pragma unroll
                for (int j = TOPK - 1; j > 0; --j) {
                    if (best[j] > best[j - 1]) {
                        float tv = best[j]; best[j] = best[j - 1]; best[j - 1] = tv;
                        int   ti = bidx[j]; bidx[j] = bidx[j - 1]; bidx[j - 1] = ti;
                    }
                }
            }
        }
        float mx = best[0];
        float s = 0.0f;
        unsigned long long mask = 0ULL;
#pragma unroll
        for (int i = 0; i < TOPK; ++i) {
            s += expf(best[i] - mx);
            mask |= 1ULL << bidx[i];
        }
        s_max[tid]  = mx;
        s_inv[tid]  = 1.0f / s;
        s_mask[tid] = mask;
        if (write_indices) {
            float* oi = out_indices + (size_t)(tokBase + tid) * TOPK;
#pragma unroll
            for (int i = 0; i < TOPK; ++i) oi[i] = (float)bidx[i];
        }
    }
    __syncthreads();

    // --- sparse softmax write (coalesced) ---
    for (int i = tid; i < M_TILE * EDIM; i += 256) {
        const int t = i >> 6, e = i & 63;
        float r = 0.0f;
        if ((s_mask[t] >> e) & 1ULL)
            r = expf(Ls[t * NTOT + e] - s_max[t]) * s_inv[t];
        out_router[(size_t)(tokBase + t) * EDIM + e] = r;
    }
}

extern "C" void kernel_launch(void* const* d_in, const int* in_sizes, int n_in,
                              void* d_out, int out_size) {
    const float* x   = (const float*)d_in[0];   // (4,4096,2048)
    const float* wr  = (const float*)d_in[1];   // (64,2048)
    const float* wn  = (const float*)d_in[2];   // (64,2048)
    const float* nz  = (const float*)d_in[3];   // (4,4096,64)
    float* out = (float*)d_out;

    const int M = in_sizes[0] / CDIM;           // 16384 tokens
    const int write_idx = (out_size >= M * EDIM + M * TOPK) ? 1 : 0;
    float* out_idx = out + (size_t)M * EDIM;

    noisy_topk_router_kernel<<<M / M_TILE, 256>>>(x, wr, wn, nz, out, out_idx, write_idx);
}

// round 4
// speedup vs baseline: 2.1357x; 2.1357x over previous
#include <cuda_runtime.h>
#include <cuda_fp16.h>
#include <cstdint>

#define CDIM   2048
#define EDIM   64
#define NTOT   128          // 64 route + 64 noise outputs fused in N
#define TOPK   8
#define MT     128          // tokens per CTA
#define KC     32           // K per chunk
#define NCHUNK (CDIM / KC)  // 64

// operand scaling to keep fp16 residuals out of subnormal range
#define XSCALE   16.0f
#define WSCALE   64.0f
#define DESCALE  (1.0f / (XSCALE * WSCALE))

// smem tile geometry: rows of 32 halves (64B) padded to 80B (conflict-free ldmatrix)
#define AROW        80
#define TILE_B      (128 * AROW)        // 10240 B per operand tile
#define STAGE_B     (4 * TILE_B)        // Ahi, Alo, Bhi, Blo = 40960 B
#define SMEM_DYN    (2 * STAGE_B)       // 81920 B (reused as Ls in epilogue)
#define LS_STRIDE   129

static __device__ __forceinline__ uint32_t smem_u32(const void* p) {
    uint32_t a;
    asm("{ .reg .u64 t; cvta.to.shared.u64 t, %1; cvt.u32.u64 %0, t; }" : "=r"(a) : "l"(p));
    return a;
}
static __device__ __forceinline__ void ldm_x4(uint32_t& r0, uint32_t& r1, uint32_t& r2,
                                              uint32_t& r3, uint32_t addr) {
    asm volatile("ldmatrix.sync.aligned.m8n8.x4.shared.b16 {%0,%1,%2,%3}, [%4];"
                 : "=r"(r0), "=r"(r1), "=r"(r2), "=r"(r3) : "r"(addr));
}
static __device__ __forceinline__ void mma16816(float* c, const uint32_t* a,
                                                const uint32_t* b) {
    asm volatile(
        "mma.sync.aligned.m16n8k16.row.col.f32.f16.f16.f32 "
        "{%0,%1,%2,%3}, {%4,%5,%6,%7}, {%8,%9}, {%0,%1,%2,%3};"
        : "+f"(c[0]), "+f"(c[1]), "+f"(c[2]), "+f"(c[3])
        : "r"(a[0]), "r"(a[1]), "r"(a[2]), "r"(a[3]), "r"(b[0]), "r"(b[1]));
}
static __device__ __forceinline__ uint32_t pack2h(__half a, __half b) {
    __half2 h = __halves2half2(a, b);
    return *reinterpret_cast<uint32_t*>(&h);
}

// Scale, then split into hi/lo fp16 quads and store 8B each.
static __device__ __forceinline__ void cvt_store(char* hi, char* lo, uint32_t off,
                                                 float4 v, float scale) {
    v.x *= scale; v.y *= scale; v.z *= scale; v.w *= scale;
    __half h0 = __float2half_rn(v.x), h1 = __float2half_rn(v.y);
    __half h2 = __float2half_rn(v.z), h3 = __float2half_rn(v.w);
    float r0 = v.x - __half2float(h0), r1 = v.y - __half2float(h1);
    float r2 = v.z - __half2float(h2), r3 = v.w - __half2float(h3);
    uint2 ph = make_uint2(pack2h(h0, h1), pack2h(h2, h3));
    uint2 pl = make_uint2(pack2h(__float2half_rn(r0), __float2half_rn(r1)),
                          pack2h(__float2half_rn(r2), __float2half_rn(r3)));
    *(uint2*)(hi + off) = ph;
    *(uint2*)(lo + off) = pl;
}

__global__ __launch_bounds__(256, 1)
void router_mma_kernel(
    const float* __restrict__ x, const float* __restrict__ w_route,
    const float* __restrict__ w_noise, const float* __restrict__ noise,
    float* __restrict__ out_router, float* __restrict__ out_indices, int write_indices)
{
    extern __shared__ __align__(16) char smem[];
    __shared__ float s_max[MT];
    __shared__ float s_inv[MT];
    __shared__ unsigned long long s_msk[MT];

    const uint32_t sb = smem_u32(smem);
    const int tid = threadIdx.x;
    const int wid = tid >> 5, lane = tid & 31;
    const int wr_ = wid >> 1;            // warp row: tokens [32*wr_, +32)
    const int wc_ = wid & 1;             // warp col: outputs [64*wc_, +64)
    const int tokBase = blockIdx.x * MT;

    // fill mapping: idx = tid + 256*it (it 0..3) -> row = idx>>3 (0..127), q = idx&7
    const int f_row = tid >> 3;          // base row for it=0; +32 per it
    const int f_q   = tid & 7;

    // ldmatrix lane-address components
    const int j = lane >> 3, rr = lane & 7;
    const int a_off0 = (32 * wr_ + (j & 1) * 8 + rr) * AROW + (j >> 1) * 16;  // + mt*16*80 + ks*32
    const int b_off0 = (64 * wc_ + (j >> 1) * 8 + rr) * AROW + (j & 1) * 16;  // + p*16*80 + ks*32

    float acc[2][8][4];
#pragma unroll
    for (int mt = 0; mt < 2; ++mt)
#pragma unroll
        for (int nt = 0; nt < 8; ++nt)
#pragma unroll
            for (int k = 0; k < 4; ++k) acc[mt][nt][k] = 0.0f;

    // register prefetch buffers (chunk c+1 global data)
    float4 areg[4], breg[4];
#pragma unroll
    for (int it = 0; it < 4; ++it) {
        const int row = f_row + it * 32;
        areg[it] = *(const float4*)(x + (size_t)(tokBase + row) * CDIM + f_q * 4);
        const float* wsrc = (row < EDIM) ? (w_route + (size_t)row * CDIM)
                                         : (w_noise + (size_t)(row - EDIM) * CDIM);
        breg[it] = *(const float4*)(wsrc + f_q * 4);
    }

    for (int c = 0; c < NCHUNK; ++c) {
        const int s = c & 1;
        char* Ah = smem + s * STAGE_B;
        char* Al = Ah + TILE_B;
        char* Bh = Ah + 2 * TILE_B;
        char* Bl = Ah + 3 * TILE_B;
        // store prefetched chunk c (scaled splits)
#pragma unroll
        for (int it = 0; it < 4; ++it) {
            const uint32_t off = (uint32_t)(f_row + it * 32) * AROW + f_q * 8;
            cvt_store(Ah, Al, off, areg[it], XSCALE);
            cvt_store(Bh, Bl, off, breg[it], WSCALE);
        }
        // prefetch chunk c+1
        if (c + 1 < NCHUNK) {
            const int k0 = (c + 1) * KC;
#pragma unroll
            for (int it = 0; it < 4; ++it) {
                const int row = f_row + it * 32;
                areg[it] = *(const float4*)(x + (size_t)(tokBase + row) * CDIM + k0 + f_q * 4);
                const float* wsrc = (row < EDIM) ? (w_route + (size_t)row * CDIM)
                                                 : (w_noise + (size_t)(row - EDIM) * CDIM);
                breg[it] = *(const float4*)(wsrc + k0 + f_q * 4);
            }
        }
        __syncthreads();

        // compute chunk c from stage s
        const uint32_t ah_b = sb + s * STAGE_B;
        const uint32_t al_b = ah_b + TILE_B;
        const uint32_t bh_b = ah_b + 2 * TILE_B;
        const uint32_t bl_b = ah_b + 3 * TILE_B;
#pragma unroll
        for (int ks = 0; ks < 2; ++ks) {
            uint32_t a_hi[2][4], a_lo[2][4];
#pragma unroll
            for (int mt = 0; mt < 2; ++mt) {
                const uint32_t ao = a_off0 + mt * (16 * AROW) + ks * 32;
                ldm_x4(a_hi[mt][0], a_hi[mt][1], a_hi[mt][2], a_hi[mt][3], ah_b + ao);
                ldm_x4(a_lo[mt][0], a_lo[mt][1], a_lo[mt][2], a_lo[mt][3], al_b + ao);
            }
            uint32_t b_hi[8][2], b_lo[8][2];
#pragma unroll
            for (int p = 0; p < 4; ++p) {
                const uint32_t bo = b_off0 + p * (16 * AROW) + ks * 32;
                ldm_x4(b_hi[2 * p][0], b_hi[2 * p][1], b_hi[2 * p + 1][0], b_hi[2 * p + 1][1],
                       bh_b + bo);
                ldm_x4(b_lo[2 * p][0], b_lo[2 * p][1], b_lo[2 * p + 1][0], b_lo[2 * p + 1][1],
                       bl_b + bo);
            }
#pragma unroll
            for (int mt = 0; mt < 2; ++mt)
#pragma unroll
                for (int nt = 0; nt < 8; ++nt) {
                    mma16816(acc[mt][nt], a_hi[mt], b_hi[nt]);
                    mma16816(acc[mt][nt], a_hi[mt], b_lo[nt]);
                    mma16816(acc[mt][nt], a_lo[mt], b_hi[nt]);
                }
        }
        __syncthreads();
    }

    // --- accumulators -> Ls[token][output] (smem reuse, descaled) ---
    float* Ls = (float*)smem;
    {
        const int r0 = 32 * wr_ + (lane >> 2);
        const int c0 = 64 * wc_ + 2 * (lane & 3);
#pragma unroll
        for (int mt = 0; mt < 2; ++mt)
#pragma unroll
            for (int nt = 0; nt < 8; ++nt) {
                const int row = r0 + 16 * mt;
                const int col = c0 + 8 * nt;
                Ls[row * LS_STRIDE + col]           = acc[mt][nt][0] * DESCALE;
                Ls[row * LS_STRIDE + col + 1]       = acc[mt][nt][1] * DESCALE;
                Ls[(row + 8) * LS_STRIDE + col]     = acc[mt][nt][2] * DESCALE;
                Ls[(row + 8) * LS_STRIDE + col + 1] = acc[mt][nt][3] * DESCALE;
            }
    }
    __syncthreads();

    // --- noisy = logit + noise * softplus(noise_logit) ---
    for (int i = tid; i < MT * EDIM; i += 256) {
        const int t = i >> 6, e = i & 63;
        float l  = Ls[t * LS_STRIDE + e];
        float nl = Ls[t * LS_STRIDE + EDIM + e];
        float nz = noise[(size_t)(tokBase + t) * EDIM + e];
        float sp = fmaxf(nl, 0.0f) + log1pf(expf(-fabsf(nl)));
        Ls[t * LS_STRIDE + e] = fmaf(nz, sp, l);
    }
    __syncthreads();

    // --- per-token top-8 (stable: ties keep lower index) ---
    if (tid < MT) {
        const float* row = Ls + tid * LS_STRIDE;
        const float NEG_INF = __int_as_float(0xff800000);
        float best[TOPK]; int bidx[TOPK];
#pragma unroll
        for (int i = 0; i < TOPK; ++i) { best[i] = NEG_INF; bidx[i] = -1; }
        for (int e = 0; e < EDIM; ++e) {
            float v = row[e];
            if (v > best[TOPK - 1]) {
                best[TOPK - 1] = v; bidx[TOPK - 1] = e;
#pragma unroll
                for (int jj = TOPK - 1; jj > 0; --jj) {
                    if (best[jj] > best[jj - 1]) {
                        float tv = best[jj]; best[jj] = best[jj - 1]; best[jj - 1] = tv;
                        int ti = bidx[jj]; bidx[jj] = bidx[jj - 1]; bidx[jj - 1] = ti;
                    }
                }
            }
        }
        float mx = best[0], ssum = 0.0f;
        unsigned long long mask = 0ULL;
#pragma unroll
        for (int i = 0; i < TOPK; ++i) { ssum += expf(best[i] - mx); mask |= 1ULL << bidx[i]; }
        s_max[tid] = mx;
        s_inv[tid] = 1.0f / ssum;
        s_msk[tid] = mask;
        if (write_indices) {
            float* oi = out_indices + (size_t)(tokBase + tid) * TOPK;
#pragma unroll
            for (int i = 0; i < TOPK; ++i) oi[i] = (float)bidx[i];
        }
    }
    __syncthreads();

    // --- sparse softmax write (coalesced) ---
    for (int i = tid; i < MT * EDIM; i += 256) {
        const int t = i >> 6, e = i & 63;
        float r = 0.0f;
        if ((s_msk[t] >> e) & 1ULL)
            r = expf(Ls[t * LS_STRIDE + e] - s_max[t]) * s_inv[t];
        out_router[(size_t)(tokBase + t) * EDIM + e] = r;
    }
}

extern "C" void kernel_launch(void* const* d_in, const int* in_sizes, int n_in,
                              void* d_out, int out_size) {
    const float* x  = (const float*)d_in[0];   // (4,4096,2048)
    const float* wr = (const float*)d_in[1];   // (64,2048)
    const float* wn = (const float*)d_in[2];   // (64,2048)
    const float* nz = (const float*)d_in[3];   // (4,4096,64)
    float* out = (float*)d_out;

    const int M = in_sizes[0] / CDIM;          // 16384 tokens
    const int write_idx = (out_size >= M * EDIM + M * TOPK) ? 1 : 0;
    float* out_idx = out + (size_t)M * EDIM;

    cudaFuncSetAttribute(router_mma_kernel,
                         cudaFuncAttributeMaxDynamicSharedMemorySize, SMEM_DYN);
    router_mma_kernel<<<M / MT, 256, SMEM_DYN>>>(x, wr, wn, nz, out, out_idx, write_idx);
}

// round 5
// speedup vs baseline: 2.3852x; 1.1168x over previous
#include <cuda_runtime.h>
#include <cuda_fp16.h>
#include <cstdint>

#define CDIM   2048
#define EDIM   64
#define NTOT   128          // 64 route + 64 noise outputs fused in N
#define TOPK   8
#define MT     128          // tokens per CTA
#define KC     32           // K per chunk
#define NCHUNK (CDIM / KC)  // 64

// operand scaling to keep fp16 residuals out of subnormal range
#define XSCALE   16.0f
#define WSCALE   64.0f
#define DESCALE  (1.0f / (XSCALE * WSCALE))

// smem tile geometry: rows of 32 halves (64B) padded to 80B (conflict-free ldmatrix)
#define AROW        80
#define TILE_B      (128 * AROW)        // 10240 B per operand tile
#define STAGE_B     (4 * TILE_B)        // Ahi, Alo, Bhi, Blo = 40960 B
#define SMEM_DYN    (2 * STAGE_B)       // 81920 B (reused as Ls in epilogue)
#define LS_STRIDE   129

static __device__ __forceinline__ uint32_t smem_u32(const void* p) {
    uint32_t a;
    asm("{ .reg .u64 t; cvta.to.shared.u64 t, %1; cvt.u32.u64 %0, t; }" : "=r"(a) : "l"(p));
    return a;
}
static __device__ __forceinline__ void ldm_x4(uint32_t& r0, uint32_t& r1, uint32_t& r2,
                                              uint32_t& r3, uint32_t addr) {
    asm volatile("ldmatrix.sync.aligned.m8n8.x4.shared.b16 {%0,%1,%2,%3}, [%4];"
                 : "=r"(r0), "=r"(r1), "=r"(r2), "=r"(r3) : "r"(addr));
}
static __device__ __forceinline__ void mma16816(float* c, const uint32_t* a,
                                                const uint32_t* b) {
    asm volatile(
        "mma.sync.aligned.m16n8k16.row.col.f32.f16.f16.f32 "
        "{%0,%1,%2,%3}, {%4,%5,%6,%7}, {%8,%9}, {%0,%1,%2,%3};"
        : "+f"(c[0]), "+f"(c[1]), "+f"(c[2]), "+f"(c[3])
        : "r"(a[0]), "r"(a[1]), "r"(a[2]), "r"(a[3]), "r"(b[0]), "r"(b[1]));
}
static __device__ __forceinline__ uint32_t pack2h(__half a, __half b) {
    __half2 h = __halves2half2(a, b);
    return *reinterpret_cast<uint32_t*>(&h);
}

// Scale, then split into hi/lo fp16 quads and store 8B each.
static __device__ __forceinline__ void cvt_store(char* hi, char* lo, uint32_t off,
                                                 float4 v, float scale) {
    v.x *= scale; v.y *= scale; v.z *= scale; v.w *= scale;
    __half h0 = __float2half_rn(v.x), h1 = __float2half_rn(v.y);
    __half h2 = __float2half_rn(v.z), h3 = __float2half_rn(v.w);
    float r0 = v.x - __half2float(h0), r1 = v.y - __half2float(h1);
    float r2 = v.z - __half2float(h2), r3 = v.w - __half2float(h3);
    uint2 ph = make_uint2(pack2h(h0, h1), pack2h(h2, h3));
    uint2 pl = make_uint2(pack2h(__float2half_rn(r0), __float2half_rn(r1)),
                          pack2h(__float2half_rn(r2), __float2half_rn(r3)));
    *(uint2*)(hi + off) = ph;
    *(uint2*)(lo + off) = pl;
}

__global__ __launch_bounds__(256, 1)
void router_mma_kernel(
    const float* __restrict__ x, const float* __restrict__ w_route,
    const float* __restrict__ w_noise, const float* __restrict__ noise,
    float* __restrict__ out_router, float* __restrict__ out_indices, int write_indices)
{
    extern __shared__ __align__(16) char smem[];
    __shared__ float s_max[MT];
    __shared__ float s_inv[MT];
    __shared__ unsigned long long s_msk[MT];

    const uint32_t sb = smem_u32(smem);
    const int tid = threadIdx.x;
    const int wid = tid >> 5, lane = tid & 31;
    const int wr_ = wid >> 1;            // warp row: tokens [32*wr_, +32)
    const int wc_ = wid & 1;             // warp col: outputs [64*wc_, +64)
    const int tokBase = blockIdx.x * MT;

    // fill mapping: idx = tid + 256*it (it 0..3) -> row = idx>>3 (0..127), q = idx&7
    const int f_row = tid >> 3;
    const int f_q   = tid & 7;

    // ldmatrix lane-address components
    const int j = lane >> 3, rr = lane & 7;
    const int a_off0 = (32 * wr_ + (j & 1) * 8 + rr) * AROW + (j >> 1) * 16;
    const int b_off0 = (64 * wc_ + (j >> 1) * 8 + rr) * AROW + (j & 1) * 16;

    float acc[2][8][4];
#pragma unroll
    for (int mt = 0; mt < 2; ++mt)
#pragma unroll
        for (int nt = 0; nt < 8; ++nt)
#pragma unroll
            for (int k = 0; k < 4; ++k) acc[mt][nt][k] = 0.0f;

    // ---- prologue: load chunk 0 and publish it to stage 0 ----
    float4 areg[4], breg[4];
#pragma unroll
    for (int it = 0; it < 4; ++it) {
        const int row = f_row + it * 32;
        areg[it] = *(const float4*)(x + (size_t)(tokBase + row) * CDIM + f_q * 4);
        const float* wsrc = (row < EDIM) ? (w_route + (size_t)row * CDIM)
                                         : (w_noise + (size_t)(row - EDIM) * CDIM);
        breg[it] = *(const float4*)(wsrc + f_q * 4);
    }
#pragma unroll
    for (int it = 0; it < 4; ++it) {
        const uint32_t off = (uint32_t)(f_row + it * 32) * AROW + f_q * 8;
        cvt_store(smem, smem + TILE_B, off, areg[it], XSCALE);
        cvt_store(smem + 2 * TILE_B, smem + 3 * TILE_B, off, breg[it], WSCALE);
    }
    __syncthreads();

    // ---- mainloop: prefetch(c+1) || compute(c) || cvt_store(c+1), one sync ----
    for (int c = 0; c < NCHUNK; ++c) {
        const int s = c & 1;
        const int has_next = (c + 1 < NCHUNK);

        // issue global prefetch for chunk c+1 early
        if (has_next) {
            const int k0 = (c + 1) * KC;
#pragma unroll
            for (int it = 0; it < 4; ++it) {
                const int row = f_row + it * 32;
                areg[it] = *(const float4*)(x + (size_t)(tokBase + row) * CDIM + k0 + f_q * 4);
                const float* wsrc = (row < EDIM) ? (w_route + (size_t)row * CDIM)
                                                 : (w_noise + (size_t)(row - EDIM) * CDIM);
                breg[it] = *(const float4*)(wsrc + k0 + f_q * 4);
            }
        }

        // compute chunk c from stage s (independent of the cvt/STS below ->
        // scheduler interleaves fill work into HMMA shadow latency)
        const uint32_t ah_b = sb + s * STAGE_B;
        const uint32_t al_b = ah_b + TILE_B;
        const uint32_t bh_b = ah_b + 2 * TILE_B;
        const uint32_t bl_b = ah_b + 3 * TILE_B;
#pragma unroll
        for (int ks = 0; ks < 2; ++ks) {
            uint32_t a_hi[2][4], a_lo[2][4];
#pragma unroll
            for (int mt = 0; mt < 2; ++mt) {
                const uint32_t ao = a_off0 + mt * (16 * AROW) + ks * 32;
                ldm_x4(a_hi[mt][0], a_hi[mt][1], a_hi[mt][2], a_hi[mt][3], ah_b + ao);
                ldm_x4(a_lo[mt][0], a_lo[mt][1], a_lo[mt][2], a_lo[mt][3], al_b + ao);
            }
            uint32_t b_hi[8][2], b_lo[8][2];
#pragma unroll
            for (int p = 0; p < 4; ++p) {
                const uint32_t bo = b_off0 + p * (16 * AROW) + ks * 32;
                ldm_x4(b_hi[2 * p][0], b_hi[2 * p][1], b_hi[2 * p + 1][0], b_hi[2 * p + 1][1],
                       bh_b + bo);
                ldm_x4(b_lo[2 * p][0], b_lo[2 * p][1], b_lo[2 * p + 1][0], b_lo[2 * p + 1][1],
                       bl_b + bo);
            }
#pragma unroll
            for (int mt = 0; mt < 2; ++mt)
#pragma unroll
                for (int nt = 0; nt < 8; ++nt) {
                    mma16816(acc[mt][nt], a_hi[mt], b_hi[nt]);
                    mma16816(acc[mt][nt], a_hi[mt], b_lo[nt]);
                    mma16816(acc[mt][nt], a_lo[mt], b_hi[nt]);
                }
        }

        // publish chunk c+1 into the other stage (last read fenced by prev sync)
        if (has_next) {
            char* Ah = smem + (1 - s) * STAGE_B;
#pragma unroll
            for (int it = 0; it < 4; ++it) {
                const uint32_t off = (uint32_t)(f_row + it * 32) * AROW + f_q * 8;
                cvt_store(Ah, Ah + TILE_B, off, areg[it], XSCALE);
                cvt_store(Ah + 2 * TILE_B, Ah + 3 * TILE_B, off, breg[it], WSCALE);
            }
        }
        __syncthreads();
    }

    // --- accumulators -> Ls[token][output] (smem reuse, descaled) ---
    float* Ls = (float*)smem;
    {
        const int r0 = 32 * wr_ + (lane >> 2);
        const int c0 = 64 * wc_ + 2 * (lane & 3);
#pragma unroll
        for (int mt = 0; mt < 2; ++mt)
#pragma unroll
            for (int nt = 0; nt < 8; ++nt) {
                const int row = r0 + 16 * mt;
                const int col = c0 + 8 * nt;
                Ls[row * LS_STRIDE + col]           = acc[mt][nt][0] * DESCALE;
                Ls[row * LS_STRIDE + col + 1]       = acc[mt][nt][1] * DESCALE;
                Ls[(row + 8) * LS_STRIDE + col]     = acc[mt][nt][2] * DESCALE;
                Ls[(row + 8) * LS_STRIDE + col + 1] = acc[mt][nt][3] * DESCALE;
            }
    }
    __syncthreads();

    // --- noisy = logit + noise * softplus(noise_logit) ---
    for (int i = tid; i < MT * EDIM; i += 256) {
        const int t = i >> 6, e = i & 63;
        float l  = Ls[t * LS_STRIDE + e];
        float nl = Ls[t * LS_STRIDE + EDIM + e];
        float nz = noise[(size_t)(tokBase + t) * EDIM + e];
        float sp = fmaxf(nl, 0.0f) + log1pf(expf(-fabsf(nl)));
        Ls[t * LS_STRIDE + e] = fmaf(nz, sp, l);
    }
    __syncthreads();

    // --- per-token top-8 (stable: ties keep lower index) ---
    if (tid < MT) {
        const float* row = Ls + tid * LS_STRIDE;
        const float NEG_INF = __int_as_float(0xff800000);
        float best[TOPK]; int bidx[TOPK];
#pragma unroll
        for (int i = 0; i < TOPK; ++i) { best[i] = NEG_INF; bidx[i] = -1; }
        for (int e = 0; e < EDIM; ++e) {
            float v = row[e];
            if (v > best[TOPK - 1]) {
                best[TOPK - 1] = v; bidx[TOPK - 1] = e;
#pragma unroll
                for (int jj = TOPK - 1; jj > 0; --jj) {
                    if (best[jj] > best[jj - 1]) {
                        float tv = best[jj]; best[jj] = best[jj - 1]; best[jj - 1] = tv;
                        int ti = bidx[jj]; bidx[jj] = bidx[jj - 1]; bidx[jj - 1] = ti;
                    }
                }
            }
        }
        float mx = best[0], ssum = 0.0f;
        unsigned long long mask = 0ULL;
#pragma unroll
        for (int i = 0; i < TOPK; ++i) { ssum += expf(best[i] - mx); mask |= 1ULL << bidx[i]; }
        s_max[tid] = mx;
        s_inv[tid] = 1.0f / ssum;
        s_msk[tid] = mask;
        if (write_indices) {
            float* oi = out_indices + (size_t)(tokBase + tid) * TOPK;
#pragma unroll
            for (int i = 0; i < TOPK; ++i) oi[i] = (float)bidx[i];
        }
    }
    __syncthreads();

    // --- sparse softmax write (coalesced) ---
    for (int i = tid; i < MT * EDIM; i += 256) {
        const int t = i >> 6, e = i & 63;
        float r = 0.0f;
        if ((s_msk[t] >> e) & 1ULL)
            r = expf(Ls[t * LS_STRIDE + e] - s_max[t]) * s_inv[t];
        out_router[(size_t)(tokBase + t) * EDIM + e] = r;
    }
}

extern "C" void kernel_launch(void* const* d_in, const int* in_sizes, int n_in,
                              void* d_out, int out_size) {
    const float* x  = (const float*)d_in[0];   // (4,4096,2048)
    const float* wr = (const float*)d_in[1];   // (64,2048)
    const float* wn = (const float*)d_in[2];   // (64,2048)
    const float* nz = (const float*)d_in[3];   // (4,4096,64)
    float* out = (float*)d_out;

    const int M = in_sizes[0] / CDIM;          // 16384 tokens
    const int write_idx = (out_size >= M * EDIM + M * TOPK) ? 1 : 0;
    float* out_idx = out + (size_t)M * EDIM;

    cudaFuncSetAttribute(router_mma_kernel,
                         cudaFuncAttributeMaxDynamicSharedMemorySize, SMEM_DYN);
    router_mma_kernel<<<M / MT, 256, SMEM_DYN>>>(x, wr, wn, nz, out, out_idx, write_idx);
}